// round 10
// baseline (speedup 1.0000x reference)
#include <cuda_runtime.h>

// Problem constants
#define BATCH 32
#define CH    64
#define HW    128
#define CHW   (HW*HW)
#define NK    4
#define TAPS  9
#define CIK   (CH*TAPS)        // 576
#define CI_CHUNK 4
#define NCHUNK  (CH/CI_CHUNK)  // 16
#define WCHUNK  (CI_CHUNK*CIK) // 2304 floats per weight chunk
#define NROWS   4              // staged input rows per ci (y0-1..y0+2)
#define ISLOT   (CI_CHUNK*NROWS*130) // 2080 input staging slots per chunk

// Scratch (device globals: no allocation allowed)
// g_wmix layout: [b][ci][tap][co]  (co contiguous)
__device__ float g_wmix[BATCH * CH * TAPS * CH];
__device__ float g_bmix[BATCH * CH];

// ---------------------------------------------------------------------------
// Kernel 1: mix weight bank + bias per sample
// ---------------------------------------------------------------------------
__global__ void __launch_bounds__(256) mix_kernel(
    const float* __restrict__ att,     // [B, NK]
    const float* __restrict__ weight,  // [NK, C, C, 3, 3]
    const float* __restrict__ bias)    // [NK, C]
{
    int gid = blockIdx.x * 256 + threadIdx.x;
    const int TOT = BATCH * CH * TAPS * CH;
    if (gid < TOT) {
        int b    = gid / (CH * TAPS * CH);
        int rem  = gid - b * (CH * TAPS * CH);
        int ci   = rem / (TAPS * CH);
        int rem2 = rem - ci * (TAPS * CH);
        int tap  = rem2 >> 6;
        int co   = rem2 & 63;

        float a0 = att[b * NK + 0];
        float a1 = att[b * NK + 1];
        float a2 = att[b * NK + 2];
        float a3 = att[b * NK + 3];

        int base   = ((co * CH) + ci) * TAPS + tap;
        int stride = CH * CH * TAPS;
        g_wmix[gid] = a0 * weight[base]
                    + a1 * weight[base + stride]
                    + a2 * weight[base + 2 * stride]
                    + a3 * weight[base + 3 * stride];
    }
    if (gid < BATCH * CH) {
        int b  = gid >> 6;
        int co = gid & 63;
        float s = 0.f;
        #pragma unroll
        for (int k = 0; k < NK; k++)
            s += att[b * NK + k] * bias[k * CH + co];
        g_bmix[gid] = s;
    }
}

// ---------------------------------------------------------------------------
// Kernel 2: direct 3x3 conv, FFMA2 paired over c_out, TWO output rows/CTA.
// One CTA per (b, y-pair). 256 threads: co0=(tx>>4)*4, w0=(tx&15)*8.
// Per thread: 4 co x 8 w x 2 rows. 288 FFMA2 per c_in. Input staged as
// duplicated u64 rows (4 rows: y0-1..y0+2); each row-window loaded once
// and used by both output rows.
// ---------------------------------------------------------------------------

typedef unsigned long long u64;

__device__ __forceinline__ u64 ffma2(u64 d, u64 a, u64 b) {
    asm("fma.rn.f32x2 %0, %1, %2, %0;" : "+l"(d) : "l"(a), "l"(b));
    return d;
}
__device__ __forceinline__ u64 dup2(float v) {
    u64 p;
    asm("mov.b64 %0, {%1, %1};" : "=l"(p) : "f"(v));
    return p;
}

// Padded u64 row: 2-slot pad every 16 -> conflict-bounded strided LDS.128.
#define XU 148
__device__ __forceinline__ int DIDX(int j) { return j + ((j >> 4) << 1); }

__global__ void __launch_bounds__(256, 1) conv_kernel(
    const float* __restrict__ x,   // [B, C, H, W]
    float* __restrict__ out)       // [B, C, H, W]
{
    __shared__ alignas(16) u64   xdup[2][CI_CHUNK * NROWS * XU];
    __shared__ alignas(16) float wsf[2][WCHUNK];

    const int y0 = blockIdx.x << 1;   // output rows y0, y0+1 (blockIdx.x 0..63)
    const int b  = blockIdx.y;
    const int tx = threadIdx.x;

    const int co0 = (tx >> 4) << 2;  // 0..60 step 4
    const int w0  = (tx & 15) << 3;  // 0..120 step 8

    // LDS offsets for the 5 input .128 loads (u64 idx, 16B aligned)
    int xoff[5];
    #pragma unroll
    for (int i = 0; i < 5; i++) xoff[i] = DIDX(w0 + 2 * i);

    // ---- input staging map: 9 slots per thread (last guarded) ----
    int  gofs[9], sofs[9];
    bool val[9], act[9];
    #pragma unroll
    for (int k = 0; k < 9; k++) {
        int s = tx + k * 256;
        act[k] = (s < ISLOT);
        int ss  = act[k] ? s : 0;
        int ci4 = ss / (NROWS * 130);
        int rem = ss - (NROWS * 130) * ci4;
        int r   = rem / 130;
        int c   = rem - 130 * r;
        int yy  = y0 - 1 + r;
        int col = c - 1;
        val[k]  = act[k] && ((unsigned)yy < HW) && ((unsigned)col < HW);
        gofs[k] = ci4 * CHW + yy * HW + col;
        sofs[k] = (ci4 * NROWS + r) * XU + DIDX(c);
    }

    // Accumulators: [row][co-pair][w-pair], init with mixed bias
    u64 acc[2][2][8];
    #pragma unroll
    for (int cp = 0; cp < 2; cp++) {
        u64 bp = *reinterpret_cast<const u64*>(g_bmix + b * CH + co0 + 2 * cp);
        #pragma unroll
        for (int wi = 0; wi < 8; wi++) { acc[0][cp][wi] = bp; acc[1][cp][wi] = bp; }
    }

    const float* xbase = x + (size_t)(b * CH) * CHW;
    const float* wbase = g_wmix + (size_t)(b * CH) * TAPS * CH;

    // ---- prologue: stage chunk 0 into buffer 0 ----
    {
        #pragma unroll
        for (int k = 0; k < 9; k++)
            if (act[k]) xdup[0][sofs[k]] = dup2(val[k] ? __ldg(xbase + gofs[k]) : 0.f);
        #pragma unroll
        for (int k = 0; k < 9; k++)
            wsf[0][tx + k * 256] = __ldg(wbase + tx + k * 256);
    }
    __syncthreads();

    #pragma unroll 1
    for (int chunk = 0; chunk < NCHUNK; chunk++) {
        const int p = chunk & 1;

        // --- prefetch next chunk into registers ---
        float pin[9], pwt[9];
        if (chunk + 1 < NCHUNK) {
            const float* xc = xbase + (chunk + 1) * CI_CHUNK * CHW;
            #pragma unroll
            for (int k = 0; k < 9; k++)
                pin[k] = val[k] ? __ldg(xc + gofs[k]) : 0.f;
            const float* wc = wbase + (chunk + 1) * WCHUNK;
            #pragma unroll
            for (int k = 0; k < 9; k++)
                pwt[k] = __ldg(wc + tx + k * 256);
        }

        // --- compute 4 ci from buffer p ---
        #pragma unroll
        for (int ci4 = 0; ci4 < CI_CHUNK; ci4++) {
            const float* wr = wsf[p] + ci4 * CIK;
            const u64*   xb = xdup[p] + ci4 * NROWS * XU;
            // walk the 4 input rows; row r feeds (yout=0, ky=r) and (yout=1, ky=r-1)
            #pragma unroll
            for (int r = 0; r < NROWS; r++) {
                const u64* xr = xb + r * XU;
                u64 xw[10];
                #pragma unroll
                for (int i = 0; i < 5; i++) {
                    ulonglong2 q = *reinterpret_cast<const ulonglong2*>(xr + xoff[i]);
                    xw[2 * i] = q.x; xw[2 * i + 1] = q.y;
                }
                if (r < 3) {  // output row 0, ky = r
                    #pragma unroll
                    for (int kx = 0; kx < 3; kx++) {
                        ulonglong2 wv = *reinterpret_cast<const ulonglong2*>(
                            wr + (r * 3 + kx) * CH + co0);  // warp-broadcast
                        #pragma unroll
                        for (int wi = 0; wi < 8; wi++) {
                            acc[0][0][wi] = ffma2(acc[0][0][wi], wv.x, xw[kx + wi]);
                            acc[0][1][wi] = ffma2(acc[0][1][wi], wv.y, xw[kx + wi]);
                        }
                    }
                }
                if (r >= 1) {  // output row 1, ky = r-1
                    #pragma unroll
                    for (int kx = 0; kx < 3; kx++) {
                        ulonglong2 wv = *reinterpret_cast<const ulonglong2*>(
                            wr + ((r - 1) * 3 + kx) * CH + co0);
                        #pragma unroll
                        for (int wi = 0; wi < 8; wi++) {
                            acc[1][0][wi] = ffma2(acc[1][0][wi], wv.x, xw[kx + wi]);
                            acc[1][1][wi] = ffma2(acc[1][1][wi], wv.y, xw[kx + wi]);
                        }
                    }
                }
            }
        }

        // --- store prefetch into the other buffer ---
        if (chunk + 1 < NCHUNK) {
            u64*   xd = xdup[p ^ 1];
            float* wd = wsf[p ^ 1];
            #pragma unroll
            for (int k = 0; k < 9; k++)
                if (act[k]) xd[sofs[k]] = dup2(pin[k]);
            #pragma unroll
            for (int k = 0; k < 9; k++)
                wd[tx + k * 256] = pwt[k];
        }
        __syncthreads();
    }

    // --- stores: 2 rows x 4 co x 8 w per thread ---
    union Cv { u64 u; float2 f; };
    #pragma unroll
    for (int row = 0; row < 2; row++) {
        #pragma unroll
        for (int cp = 0; cp < 2; cp++) {
            Cv v[8];
            #pragma unroll
            for (int wi = 0; wi < 8; wi++) v[wi].u = acc[row][cp][wi];
            #pragma unroll
            for (int half = 0; half < 2; half++) {
                int co = co0 + 2 * cp + half;
                float* o = out + (((size_t)(b * CH + co) * HW) + y0 + row) * HW + w0;
                float4 s0, s1;
                if (half == 0) {
                    s0 = make_float4(v[0].f.x, v[1].f.x, v[2].f.x, v[3].f.x);
                    s1 = make_float4(v[4].f.x, v[5].f.x, v[6].f.x, v[7].f.x);
                } else {
                    s0 = make_float4(v[0].f.y, v[1].f.y, v[2].f.y, v[3].f.y);
                    s1 = make_float4(v[4].f.y, v[5].f.y, v[6].f.y, v[7].f.y);
                }
                *reinterpret_cast<float4*>(o)     = s0;
                *reinterpret_cast<float4*>(o + 4) = s1;
            }
        }
    }
}

// ---------------------------------------------------------------------------
// Launch. Inputs: x, attention, weight, bias_p.
// ---------------------------------------------------------------------------
extern "C" void kernel_launch(void* const* d_in, const int* in_sizes, int n_in,
                              void* d_out, int out_size)
{
    const float* x    = (const float*)d_in[0];  // [32,64,128,128]
    const float* att  = (const float*)d_in[1];  // [32,4]
    const float* wgt  = (const float*)d_in[2];  // [4,64,64,3,3]
    const float* bias = (const float*)d_in[3];  // [4,64]
    float* out = (float*)d_out;

    const int TOT = BATCH * CH * TAPS * CH;
    mix_kernel<<<(TOT + 255) / 256, 256>>>(att, wgt, bias);

    dim3 grid(HW / 2, BATCH);  // (y-pair, b)
    conv_kernel<<<grid, 256>>>(x, out);
}

// round 11
// speedup vs baseline: 1.7605x; 1.7605x over previous
#include <cuda_runtime.h>

// Problem constants
#define BATCH 32
#define CH    64
#define HW    128
#define CHW   (HW*HW)
#define NK    4
#define TAPS  9
#define CIK   (CH*TAPS)        // 576
#define CI_CHUNK 2
#define NCHUNK  (CH/CI_CHUNK)    // 32
#define WCHUNK  (CI_CHUNK*CIK)   // 1152 floats per weight chunk
#define ISLOT   (CI_CHUNK*3*130) // 780 input staging slots per chunk

// Scratch (device globals: no allocation allowed)
// g_wmix layout: [b][ci][tap][co]  (co contiguous)
__device__ float g_wmix[BATCH * CH * TAPS * CH];
__device__ float g_bmix[BATCH * CH];

// ---------------------------------------------------------------------------
// Kernel 1: mix weight bank + bias per sample
// ---------------------------------------------------------------------------
__global__ void __launch_bounds__(256) mix_kernel(
    const float* __restrict__ att,     // [B, NK]
    const float* __restrict__ weight,  // [NK, C, C, 3, 3]
    const float* __restrict__ bias)    // [NK, C]
{
    int gid = blockIdx.x * 256 + threadIdx.x;
    const int TOT = BATCH * CH * TAPS * CH;
    if (gid < TOT) {
        int b    = gid / (CH * TAPS * CH);
        int rem  = gid - b * (CH * TAPS * CH);
        int ci   = rem / (TAPS * CH);
        int rem2 = rem - ci * (TAPS * CH);
        int tap  = rem2 >> 6;
        int co   = rem2 & 63;

        float a0 = att[b * NK + 0];
        float a1 = att[b * NK + 1];
        float a2 = att[b * NK + 2];
        float a3 = att[b * NK + 3];

        int base   = ((co * CH) + ci) * TAPS + tap;
        int stride = CH * CH * TAPS;
        g_wmix[gid] = a0 * weight[base]
                    + a1 * weight[base + stride]
                    + a2 * weight[base + 2 * stride]
                    + a3 * weight[base + 3 * stride];
    }
    if (gid < BATCH * CH) {
        int b  = gid >> 6;
        int co = gid & 63;
        float s = 0.f;
        #pragma unroll
        for (int k = 0; k < NK; k++)
            s += att[b * NK + k] * bias[k * CH + co];
        g_bmix[gid] = s;
    }
}

// ---------------------------------------------------------------------------
// Kernel 2: direct 3x3 conv, FFMA2 paired over c_out, 8 c_out per thread.
// One CTA per (b, y). 128 threads: co0=(tx>>4)*8 (4 co-pairs), w0=(tx&15)*8.
// 288 FFMA2 per c_in per thread. Input staged duplicated (u64 = {v,v});
// weight pairs are adjacent floats, warp-broadcast LDS.128.
// 2-ci chunks, double-buffered, 1 barrier/chunk.
// ---------------------------------------------------------------------------

typedef unsigned long long u64;

__device__ __forceinline__ u64 ffma2(u64 d, u64 a, u64 b) {
    asm("fma.rn.f32x2 %0, %1, %2, %0;" : "+l"(d) : "l"(a), "l"(b));
    return d;
}
__device__ __forceinline__ u64 dup2(float v) {
    u64 p;
    asm("mov.b64 %0, {%1, %1};" : "=l"(p) : "f"(v));
    return p;
}

// Padded u64 row: 2-slot pad every 16 -> conflict-bounded strided LDS.128.
#define XU 148
__device__ __forceinline__ int DIDX(int j) { return j + ((j >> 4) << 1); }

__global__ void __launch_bounds__(128, 3) conv_kernel(
    const float* __restrict__ x,   // [B, C, H, W]
    float* __restrict__ out)       // [B, C, H, W]
{
    __shared__ alignas(16) u64   xdup[2][CI_CHUNK * 3 * XU];  // 14.2 KB
    __shared__ alignas(16) float wsf[2][WCHUNK];              //  9.2 KB

    const int y  = blockIdx.x;
    const int b  = blockIdx.y;
    const int tx = threadIdx.x;

    const int co0 = (tx >> 4) << 3;  // 0..56 step 8
    const int w0  = (tx & 15) << 3;  // 0..120 step 8

    // LDS offsets for the 5 input .128 loads (u64 idx, 16B aligned)
    int xoff[5];
    #pragma unroll
    for (int i = 0; i < 5; i++) xoff[i] = DIDX(w0 + 2 * i);

    // ---- input staging map: 7 slots per thread (last guarded) ----
    int  gofs[7], sofs[7];
    bool val[7], act[7];
    #pragma unroll
    for (int k = 0; k < 7; k++) {
        int s = tx + k * 128;
        act[k] = (s < ISLOT);
        int ss  = act[k] ? s : 0;
        int ci2 = ss / 390;
        int rem = ss - 390 * ci2;
        int r   = rem / 130;
        int c   = rem - 130 * r;
        int yy  = y - 1 + r;
        int col = c - 1;
        val[k]  = act[k] && ((unsigned)yy < HW) && ((unsigned)col < HW);
        gofs[k] = ci2 * CHW + yy * HW + col;
        sofs[k] = (ci2 * 3 + r) * XU + DIDX(c);
    }

    // Accumulators: 4 co-pairs x 8 w, init with mixed bias
    u64 acc[4][8];
    #pragma unroll
    for (int cp = 0; cp < 4; cp++) {
        u64 bp = *reinterpret_cast<const u64*>(g_bmix + b * CH + co0 + 2 * cp);
        #pragma unroll
        for (int wi = 0; wi < 8; wi++) acc[cp][wi] = bp;
    }

    const float* xbase = x + (size_t)(b * CH) * CHW;
    const float* wbase = g_wmix + (size_t)(b * CH) * TAPS * CH;

    // ---- prologue: stage chunk 0 into buffer 0 ----
    {
        #pragma unroll
        for (int k = 0; k < 7; k++)
            if (act[k]) xdup[0][sofs[k]] = dup2(val[k] ? __ldg(xbase + gofs[k]) : 0.f);
        #pragma unroll
        for (int k = 0; k < 9; k++)
            wsf[0][tx + k * 128] = __ldg(wbase + tx + k * 128);
    }
    __syncthreads();

    #pragma unroll 1
    for (int chunk = 0; chunk < NCHUNK; chunk++) {
        const int p = chunk & 1;

        // --- prefetch next chunk into registers ---
        float pin[7], pwt[9];
        if (chunk + 1 < NCHUNK) {
            const float* xc = xbase + (chunk + 1) * CI_CHUNK * CHW;
            #pragma unroll
            for (int k = 0; k < 7; k++)
                pin[k] = val[k] ? __ldg(xc + gofs[k]) : 0.f;
            const float* wc = wbase + (chunk + 1) * WCHUNK;
            #pragma unroll
            for (int k = 0; k < 9; k++)
                pwt[k] = __ldg(wc + tx + k * 128);
        }

        // --- compute 2 ci from buffer p ---
        #pragma unroll
        for (int ci2 = 0; ci2 < CI_CHUNK; ci2++) {
            const float* wr = wsf[p] + ci2 * CIK;
            const u64*   xb = xdup[p] + ci2 * 3 * XU;
            #pragma unroll
            for (int ky = 0; ky < 3; ky++) {
                const u64* xr = xb + ky * XU;
                u64 xw[10];
                #pragma unroll
                for (int i = 0; i < 5; i++) {
                    ulonglong2 q = *reinterpret_cast<const ulonglong2*>(xr + xoff[i]);
                    xw[2 * i] = q.x; xw[2 * i + 1] = q.y;
                }
                #pragma unroll
                for (int kx = 0; kx < 3; kx++) {
                    const float* wt = wr + (ky * 3 + kx) * CH + co0;
                    ulonglong2 wa = *reinterpret_cast<const ulonglong2*>(wt);      // co0..+3
                    ulonglong2 wb2 = *reinterpret_cast<const ulonglong2*>(wt + 4); // co0+4..+7
                    #pragma unroll
                    for (int wi = 0; wi < 8; wi++) {
                        acc[0][wi] = ffma2(acc[0][wi], wa.x,  xw[kx + wi]);
                        acc[1][wi] = ffma2(acc[1][wi], wa.y,  xw[kx + wi]);
                        acc[2][wi] = ffma2(acc[2][wi], wb2.x, xw[kx + wi]);
                        acc[3][wi] = ffma2(acc[3][wi], wb2.y, xw[kx + wi]);
                    }
                }
            }
        }

        // --- store prefetch into the other buffer ---
        if (chunk + 1 < NCHUNK) {
            u64*   xd = xdup[p ^ 1];
            float* wd = wsf[p ^ 1];
            #pragma unroll
            for (int k = 0; k < 7; k++)
                if (act[k]) xd[sofs[k]] = dup2(pin[k]);
            #pragma unroll
            for (int k = 0; k < 9; k++)
                wd[tx + k * 128] = pwt[k];
        }
        __syncthreads();
    }

    // --- stores: 8 co x 8 w per thread ---
    union Cv { u64 u; float2 f; };
    #pragma unroll
    for (int cp = 0; cp < 4; cp++) {
        Cv v[8];
        #pragma unroll
        for (int wi = 0; wi < 8; wi++) v[wi].u = acc[cp][wi];
        #pragma unroll
        for (int half = 0; half < 2; half++) {
            int co = co0 + 2 * cp + half;
            float* o = out + (((size_t)(b * CH + co) * HW) + y) * HW + w0;
            float4 s0, s1;
            if (half == 0) {
                s0 = make_float4(v[0].f.x, v[1].f.x, v[2].f.x, v[3].f.x);
                s1 = make_float4(v[4].f.x, v[5].f.x, v[6].f.x, v[7].f.x);
            } else {
                s0 = make_float4(v[0].f.y, v[1].f.y, v[2].f.y, v[3].f.y);
                s1 = make_float4(v[4].f.y, v[5].f.y, v[6].f.y, v[7].f.y);
            }
            *reinterpret_cast<float4*>(o)     = s0;
            *reinterpret_cast<float4*>(o + 4) = s1;
        }
    }
}

// ---------------------------------------------------------------------------
// Launch. Inputs: x, attention, weight, bias_p.
// ---------------------------------------------------------------------------
extern "C" void kernel_launch(void* const* d_in, const int* in_sizes, int n_in,
                              void* d_out, int out_size)
{
    const float* x    = (const float*)d_in[0];  // [32,64,128,128]
    const float* att  = (const float*)d_in[1];  // [32,4]
    const float* wgt  = (const float*)d_in[2];  // [4,64,64,3,3]
    const float* bias = (const float*)d_in[3];  // [4,64]
    float* out = (float*)d_out;

    const int TOT = BATCH * CH * TAPS * CH;
    mix_kernel<<<(TOT + 255) / 256, 256>>>(att, wgt, bias);

    dim3 grid(HW, BATCH);  // (y, b)
    conv_kernel<<<grid, 128>>>(x, out);
}

// round 13
// speedup vs baseline: 1.8988x; 1.0786x over previous
#include <cuda_runtime.h>
#include <cstdint>

// Problem constants
#define BATCH 32
#define CH    64
#define HW    128
#define CHW   (HW*HW)
#define NK    4
#define TAPS  9
#define CIK   (CH*TAPS)        // 576
#define CI_CHUNK 2
#define NCHUNK  (CH/CI_CHUNK)    // 32
#define WCHUNK  (CI_CHUNK*CIK)   // 1152 floats per weight chunk
#define ISLOT   (CI_CHUNK*3*130) // 780 input staging slots per chunk

// Scratch (device globals: no allocation allowed)
// g_wmix layout: [b][ci][tap][co]  (co contiguous)
__device__ float g_wmix[BATCH * CH * TAPS * CH];
__device__ float g_bmix[BATCH * CH];

// ---------------------------------------------------------------------------
// Kernel 1: mix weight bank + bias per sample
// ---------------------------------------------------------------------------
__global__ void __launch_bounds__(256) mix_kernel(
    const float* __restrict__ att,     // [B, NK]
    const float* __restrict__ weight,  // [NK, C, C, 3, 3]
    const float* __restrict__ bias)    // [NK, C]
{
    int gid = blockIdx.x * 256 + threadIdx.x;
    const int TOT = BATCH * CH * TAPS * CH;
    if (gid < TOT) {
        int b    = gid / (CH * TAPS * CH);
        int rem  = gid - b * (CH * TAPS * CH);
        int ci   = rem / (TAPS * CH);
        int rem2 = rem - ci * (TAPS * CH);
        int tap  = rem2 >> 6;
        int co   = rem2 & 63;

        float a0 = att[b * NK + 0];
        float a1 = att[b * NK + 1];
        float a2 = att[b * NK + 2];
        float a3 = att[b * NK + 3];

        int base   = ((co * CH) + ci) * TAPS + tap;
        int stride = CH * CH * TAPS;
        g_wmix[gid] = a0 * weight[base]
                    + a1 * weight[base + stride]
                    + a2 * weight[base + 2 * stride]
                    + a3 * weight[base + 3 * stride];
    }
    if (gid < BATCH * CH) {
        int b  = gid >> 6;
        int co = gid & 63;
        float s = 0.f;
        #pragma unroll
        for (int k = 0; k < NK; k++)
            s += att[b * NK + k] * bias[k * CH + co];
        g_bmix[gid] = s;
    }
}

// ---------------------------------------------------------------------------
// Kernel 2: direct 3x3 conv, FFMA2 paired over c_out, 8 c_out per thread.
// One CTA per (b, y). 128 threads: co0=(tx>>4)*8 (4 co-pairs), w0=(tx&15)*8.
// 288 FFMA2 per c_in per thread. Inputs staged duplicated (u64={v,v}) via
// register prefetch; weights staged via cp.async (no regs, no LDG/STS pairs).
// 2-ci chunks, double-buffered, 1 barrier/chunk. 4 CTAs/SM target.
// ---------------------------------------------------------------------------

typedef unsigned long long u64;

__device__ __forceinline__ u64 ffma2(u64 d, u64 a, u64 b) {
    asm("fma.rn.f32x2 %0, %1, %2, %0;" : "+l"(d) : "l"(a), "l"(b));
    return d;
}
__device__ __forceinline__ u64 dup2(float v) {
    u64 p;
    asm("mov.b64 %0, {%1, %1};" : "=l"(p) : "f"(v));
    return p;
}
__device__ __forceinline__ void cp_async4(unsigned saddr, const float* gaddr) {
    asm volatile("cp.async.ca.shared.global [%0], [%1], 4;"
                 :: "r"(saddr), "l"(gaddr));
}
__device__ __forceinline__ void cp_async_commit() {
    asm volatile("cp.async.commit_group;" ::: "memory");
}
__device__ __forceinline__ void cp_async_wait0() {
    asm volatile("cp.async.wait_group 0;" ::: "memory");
}

// Padded u64 row: 2-slot pad every 16 -> conflict-bounded strided LDS.128.
#define XU 148
__device__ __forceinline__ int DIDX(int j) { return j + ((j >> 4) << 1); }

__global__ void __launch_bounds__(128, 4) conv_kernel(
    const float* __restrict__ x,   // [B, C, H, W]
    float* __restrict__ out)       // [B, C, H, W]
{
    __shared__ alignas(16) u64   xdup[2][CI_CHUNK * 3 * XU];  // 14.2 KB
    __shared__ alignas(16) float wsf[2][WCHUNK];              //  9.2 KB

    const int y  = blockIdx.x;
    const int b  = blockIdx.y;
    const int tx = threadIdx.x;

    const int co0 = (tx >> 4) << 3;  // 0..56 step 8
    const int w0  = (tx & 15) << 3;  // 0..120 step 8

    // LDS offsets for the 5 input .128 loads (u64 idx, 16B aligned)
    int xoff[5];
    #pragma unroll
    for (int i = 0; i < 5; i++) xoff[i] = DIDX(w0 + 2 * i);

    // ---- input staging map: 7 slots; validity folded into sign of gofs ----
    int gofs[7], sofs[7];
    const bool act6 = (tx < ISLOT - 6 * 128);  // only k=6 is partial
    #pragma unroll
    for (int k = 0; k < 7; k++) {
        int s   = tx + k * 128;
        int ss  = (k < 6 || act6) ? s : 0;
        int ci2 = ss / 390;
        int rem = ss - 390 * ci2;
        int r   = rem / 130;
        int c   = rem - 130 * r;
        int yy  = y - 1 + r;
        int col = c - 1;
        bool v  = ((unsigned)yy < HW) && ((unsigned)col < HW);
        gofs[k] = v ? (ci2 * CHW + yy * HW + col) : -1;
        sofs[k] = (ci2 * 3 + r) * XU + DIDX(c);
    }

    // Accumulators: 4 co-pairs x 8 w, init with mixed bias
    u64 acc[4][8];
    #pragma unroll
    for (int cp = 0; cp < 4; cp++) {
        u64 bp = *reinterpret_cast<const u64*>(g_bmix + b * CH + co0 + 2 * cp);
        #pragma unroll
        for (int wi = 0; wi < 8; wi++) acc[cp][wi] = bp;
    }

    const float* xbase = x + (size_t)(b * CH) * CHW;
    const float* wbase = g_wmix + (size_t)(b * CH) * TAPS * CH;

    // ---- prologue: stage chunk 0 into buffer 0 ----
    {
        #pragma unroll
        for (int k = 0; k < 7; k++) {
            if (k < 6 || act6)
                xdup[0][sofs[k]] = dup2(gofs[k] >= 0 ? __ldg(xbase + gofs[k]) : 0.f);
        }
        #pragma unroll
        for (int k = 0; k < 9; k++) {
            unsigned sa = (unsigned)__cvta_generic_to_shared(&wsf[0][tx + k * 128]);
            cp_async4(sa, wbase + tx + k * 128);
        }
        cp_async_commit();
        cp_async_wait0();
    }
    __syncthreads();

    #pragma unroll 1
    for (int chunk = 0; chunk < NCHUNK; chunk++) {
        const int p = chunk & 1;
        const bool more = (chunk + 1 < NCHUNK);

        // --- prefetch next chunk: inputs to regs, weights via cp.async ---
        float pin[7];
        if (more) {
            const float* xc = xbase + (chunk + 1) * CI_CHUNK * CHW;
            #pragma unroll
            for (int k = 0; k < 7; k++)
                pin[k] = (gofs[k] >= 0) ? __ldg(xc + gofs[k]) : 0.f;
            const float* wc = wbase + (chunk + 1) * WCHUNK;
            #pragma unroll
            for (int k = 0; k < 9; k++) {
                unsigned sa = (unsigned)__cvta_generic_to_shared(
                    &wsf[p ^ 1][tx + k * 128]);
                cp_async4(sa, wc + tx + k * 128);
            }
            cp_async_commit();
        }

        // --- compute 2 ci from buffer p ---
        #pragma unroll
        for (int ci2 = 0; ci2 < CI_CHUNK; ci2++) {
            const float* wr = wsf[p] + ci2 * CIK;
            const u64*   xb = xdup[p] + ci2 * 3 * XU;
            #pragma unroll
            for (int ky = 0; ky < 3; ky++) {
                const u64* xr = xb + ky * XU;
                u64 xw[10];
                #pragma unroll
                for (int i = 0; i < 5; i++) {
                    ulonglong2 q = *reinterpret_cast<const ulonglong2*>(xr + xoff[i]);
                    xw[2 * i] = q.x; xw[2 * i + 1] = q.y;
                }
                #pragma unroll
                for (int kx = 0; kx < 3; kx++) {
                    const float* wt = wr + (ky * 3 + kx) * CH + co0;
                    ulonglong2 wa  = *reinterpret_cast<const ulonglong2*>(wt);
                    ulonglong2 wb2 = *reinterpret_cast<const ulonglong2*>(wt + 4);
                    #pragma unroll
                    for (int wi = 0; wi < 8; wi++) {
                        acc[0][wi] = ffma2(acc[0][wi], wa.x,  xw[kx + wi]);
                        acc[1][wi] = ffma2(acc[1][wi], wa.y,  xw[kx + wi]);
                        acc[2][wi] = ffma2(acc[2][wi], wb2.x, xw[kx + wi]);
                        acc[3][wi] = ffma2(acc[3][wi], wb2.y, xw[kx + wi]);
                    }
                }
            }
        }

        // --- store input prefetch; drain weight cp.async; publish ---
        if (more) {
            u64* xd = xdup[p ^ 1];
            #pragma unroll
            for (int k = 0; k < 7; k++) {
                if (k < 6 || act6) xd[sofs[k]] = dup2(pin[k]);
            }
            cp_async_wait0();
        }
        __syncthreads();
    }

    // --- stores: 8 co x 8 w per thread ---
    union Cv { u64 u; float2 f; };
    #pragma unroll
    for (int cp = 0; cp < 4; cp++) {
        Cv v[8];
        #pragma unroll
        for (int wi = 0; wi < 8; wi++) v[wi].u = acc[cp][wi];
        #pragma unroll
        for (int half = 0; half < 2; half++) {
            int co = co0 + 2 * cp + half;
            float* o = out + (((size_t)(b * CH + co) * HW) + y) * HW + w0;
            float4 s0, s1;
            if (half == 0) {
                s0 = make_float4(v[0].f.x, v[1].f.x, v[2].f.x, v[3].f.x);
                s1 = make_float4(v[4].f.x, v[5].f.x, v[6].f.x, v[7].f.x);
            } else {
                s0 = make_float4(v[0].f.y, v[1].f.y, v[2].f.y, v[3].f.y);
                s1 = make_float4(v[4].f.y, v[5].f.y, v[6].f.y, v[7].f.y);
            }
            *reinterpret_cast<float4*>(o)     = s0;
            *reinterpret_cast<float4*>(o + 4) = s1;
        }
    }
}

// ---------------------------------------------------------------------------
// Launch. Inputs: x, attention, weight, bias_p.
// ---------------------------------------------------------------------------
extern "C" void kernel_launch(void* const* d_in, const int* in_sizes, int n_in,
                              void* d_out, int out_size)
{
    const float* x    = (const float*)d_in[0];  // [32,64,128,128]
    const float* att  = (const float*)d_in[1];  // [32,4]
    const float* wgt  = (const float*)d_in[2];  // [4,64,64,3,3]
    const float* bias = (const float*)d_in[3];  // [4,64]
    float* out = (float*)d_out;

    const int TOT = BATCH * CH * TAPS * CH;
    mix_kernel<<<(TOT + 255) / 256, 256>>>(att, wgt, bias);

    dim3 grid(HW, BATCH);  // (y, b)
    conv_kernel<<<grid, 128>>>(x, out);
}

// round 14
// speedup vs baseline: 2.2162x; 1.1671x over previous
#include <cuda_runtime.h>
#include <cstdint>

// Problem constants
#define BATCH 32
#define CH    64
#define HW    128
#define CHW   (HW*HW)
#define NK    4
#define TAPS  9
#define CIK   (CH*TAPS)        // 576
#define CI_CHUNK 2
#define NCHUNK  (CH/CI_CHUNK)    // 32
#define WCHUNK  (CI_CHUNK*CIK)   // 1152 floats per weight chunk
#define ISLOT   (CI_CHUNK*3*130) // 780 input staging slots per chunk

// Scratch (device globals: no allocation allowed)
// g_wmix layout: [b][ci][tap][co]  (co contiguous)
__device__ float g_wmix[BATCH * CH * TAPS * CH];
__device__ float g_bmix[BATCH * CH];
__device__ float g_zero = 0.f;   // cp.async source for padded border elements

// ---------------------------------------------------------------------------
// Kernel 1: mix weight bank + bias per sample
// ---------------------------------------------------------------------------
__global__ void __launch_bounds__(256) mix_kernel(
    const float* __restrict__ att,     // [B, NK]
    const float* __restrict__ weight,  // [NK, C, C, 3, 3]
    const float* __restrict__ bias)    // [NK, C]
{
    int gid = blockIdx.x * 256 + threadIdx.x;
    const int TOT = BATCH * CH * TAPS * CH;
    if (gid < TOT) {
        int b    = gid / (CH * TAPS * CH);
        int rem  = gid - b * (CH * TAPS * CH);
        int ci   = rem / (TAPS * CH);
        int rem2 = rem - ci * (TAPS * CH);
        int tap  = rem2 >> 6;
        int co   = rem2 & 63;

        float a0 = att[b * NK + 0];
        float a1 = att[b * NK + 1];
        float a2 = att[b * NK + 2];
        float a3 = att[b * NK + 3];

        int base   = ((co * CH) + ci) * TAPS + tap;
        int stride = CH * CH * TAPS;
        g_wmix[gid] = a0 * weight[base]
                    + a1 * weight[base + stride]
                    + a2 * weight[base + 2 * stride]
                    + a3 * weight[base + 3 * stride];
    }
    if (gid < BATCH * CH) {
        int b  = gid >> 6;
        int co = gid & 63;
        float s = 0.f;
        #pragma unroll
        for (int k = 0; k < NK; k++)
            s += att[b * NK + k] * bias[k * CH + co];
        g_bmix[gid] = s;
    }
}

// ---------------------------------------------------------------------------
// Kernel 2: direct 3x3 conv, FFMA2 paired over c_out, 8 c_out per thread.
// One CTA per (b, y). 128 threads: co0=(tx>>4)*8, w0=(tx&15)*8.
// ALL staging via cp.async (weights + plain-float input rows, borders come
// from g_zero). Compute: 3 LDS per ky (10-float window) + dup2 MOVs build
// the {v,v} FFMA2 operands. 2-ci chunks, double-buffered, 1 barrier/chunk.
// ---------------------------------------------------------------------------

typedef unsigned long long u64;

__device__ __forceinline__ u64 ffma2(u64 d, u64 a, u64 b) {
    asm("fma.rn.f32x2 %0, %1, %2, %0;" : "+l"(d) : "l"(a), "l"(b));
    return d;
}
__device__ __forceinline__ u64 dup2(float v) {
    u64 p;
    asm("mov.b64 %0, {%1, %1};" : "=l"(p) : "f"(v));
    return p;
}
__device__ __forceinline__ void cp_async4(unsigned saddr, const float* gaddr) {
    asm volatile("cp.async.ca.shared.global [%0], [%1], 4;"
                 :: "r"(saddr), "l"(gaddr));
}
__device__ __forceinline__ void cp_async_commit() {
    asm volatile("cp.async.commit_group;" ::: "memory");
}
__device__ __forceinline__ void cp_async_wait0() {
    asm volatile("cp.async.wait_group 0;" ::: "memory");
}

// Plain-float padded row: insert 4-float pad every 32 floats.
// Keeps all 8-float-aligned window bases 16B-aligned and the 16 distinct
// lane addresses of a warp's LDS.128 on exactly 2 conflict-free wavefronts.
#define XR 148   // row stride in floats (max index 145, rounded to 16B mult)
__device__ __forceinline__ int XIDX4(int c) { return c + ((c >> 5) << 2); }

__global__ void __launch_bounds__(128, 4) conv_kernel(
    const float* __restrict__ x,   // [B, C, H, W]
    float* __restrict__ out)       // [B, C, H, W]
{
    __shared__ alignas(16) float xin[2][CI_CHUNK * 3 * XR];  // 7.1 KB
    __shared__ alignas(16) float wsf[2][WCHUNK];             // 9.2 KB

    const int y  = blockIdx.x;
    const int b  = blockIdx.y;
    const int tx = threadIdx.x;

    const int co0 = (tx >> 4) << 3;  // 0..56 step 8
    const int w0  = (tx & 15) << 3;  // 0..120 step 8

    // LDS float offsets for the 3 loads of the 10-float window
    const int xo0 = XIDX4(w0);
    const int xo1 = XIDX4(w0 + 4);
    const int xo2 = XIDX4(w0 + 8);

    // ---- input staging map: 7 slots; invalid -> source g_zero ----
    int gofs[7];       // global float offset within a chunk's 2-ci block (-1 = zero)
    unsigned sofs[7];  // smem byte offset within one xin buffer
    const bool act6 = (tx < ISLOT - 6 * 128);  // only k=6 is partial
    #pragma unroll
    for (int k = 0; k < 7; k++) {
        int s   = tx + k * 128;
        int ss  = (k < 6 || act6) ? s : 0;
        int ci2 = ss / 390;
        int rem = ss - 390 * ci2;
        int r   = rem / 130;
        int c   = rem - 130 * r;
        int yy  = y - 1 + r;
        int col = c - 1;
        bool v  = ((unsigned)yy < HW) && ((unsigned)col < HW);
        gofs[k] = v ? (ci2 * CHW + yy * HW + col) : -1;
        sofs[k] = (unsigned)(((ci2 * 3 + r) * XR + XIDX4(c)) * 4);
        if (!(k < 6 || act6)) sofs[k] = 0xFFFFFFFFu;  // inactive marker
    }

    // Accumulators: 4 co-pairs x 8 w, init with mixed bias
    u64 acc[4][8];
    #pragma unroll
    for (int cp = 0; cp < 4; cp++) {
        u64 bp = *reinterpret_cast<const u64*>(g_bmix + b * CH + co0 + 2 * cp);
        #pragma unroll
        for (int wi = 0; wi < 8; wi++) acc[cp][wi] = bp;
    }

    const float* xbase = x + (size_t)(b * CH) * CHW;
    const float* wbase = g_wmix + (size_t)(b * CH) * TAPS * CH;
    const unsigned xin0 = (unsigned)__cvta_generic_to_shared(&xin[0][0]);
    const unsigned xin1 = (unsigned)__cvta_generic_to_shared(&xin[1][0]);
    const unsigned wsf0 = (unsigned)__cvta_generic_to_shared(&wsf[0][0]);
    const unsigned wsf1 = (unsigned)__cvta_generic_to_shared(&wsf[1][0]);

    // ---- prologue: stage chunk 0 into buffer 0 ----
    {
        #pragma unroll
        for (int k = 0; k < 7; k++) {
            if (sofs[k] != 0xFFFFFFFFu)
                cp_async4(xin0 + sofs[k],
                          gofs[k] >= 0 ? xbase + gofs[k] : &g_zero);
        }
        #pragma unroll
        for (int k = 0; k < 9; k++)
            cp_async4(wsf0 + (tx + k * 128) * 4, wbase + tx + k * 128);
        cp_async_commit();
        cp_async_wait0();
    }
    __syncthreads();

    #pragma unroll 1
    for (int chunk = 0; chunk < NCHUNK; chunk++) {
        const int p = chunk & 1;
        const bool more = (chunk + 1 < NCHUNK);

        // --- prefetch next chunk entirely via cp.async ---
        if (more) {
            const float* xc = xbase + (chunk + 1) * CI_CHUNK * CHW;
            const unsigned xd = p ? xin0 : xin1;
            #pragma unroll
            for (int k = 0; k < 7; k++) {
                if (sofs[k] != 0xFFFFFFFFu)
                    cp_async4(xd + sofs[k],
                              gofs[k] >= 0 ? xc + gofs[k] : &g_zero);
            }
            const float* wc = wbase + (chunk + 1) * WCHUNK;
            const unsigned wd = p ? wsf0 : wsf1;
            #pragma unroll
            for (int k = 0; k < 9; k++)
                cp_async4(wd + (tx + k * 128) * 4, wc + tx + k * 128);
            cp_async_commit();
        }

        // --- compute 2 ci from buffer p ---
        #pragma unroll
        for (int ci2 = 0; ci2 < CI_CHUNK; ci2++) {
            const float* wr = wsf[p] + ci2 * CIK;
            const float* xb = xin[p] + ci2 * 3 * XR;
            #pragma unroll
            for (int ky = 0; ky < 3; ky++) {
                const float* xr = xb + ky * XR;
                float4 fa = *reinterpret_cast<const float4*>(xr + xo0);
                float4 fb = *reinterpret_cast<const float4*>(xr + xo1);
                float2 fc = *reinterpret_cast<const float2*>(xr + xo2);
                u64 xw[10];
                xw[0] = dup2(fa.x); xw[1] = dup2(fa.y);
                xw[2] = dup2(fa.z); xw[3] = dup2(fa.w);
                xw[4] = dup2(fb.x); xw[5] = dup2(fb.y);
                xw[6] = dup2(fb.z); xw[7] = dup2(fb.w);
                xw[8] = dup2(fc.x); xw[9] = dup2(fc.y);
                #pragma unroll
                for (int kx = 0; kx < 3; kx++) {
                    const float* wt = wr + (ky * 3 + kx) * CH + co0;
                    ulonglong2 wa  = *reinterpret_cast<const ulonglong2*>(wt);
                    ulonglong2 wb2 = *reinterpret_cast<const ulonglong2*>(wt + 4);
                    #pragma unroll
                    for (int wi = 0; wi < 8; wi++) {
                        acc[0][wi] = ffma2(acc[0][wi], wa.x,  xw[kx + wi]);
                        acc[1][wi] = ffma2(acc[1][wi], wa.y,  xw[kx + wi]);
                        acc[2][wi] = ffma2(acc[2][wi], wb2.x, xw[kx + wi]);
                        acc[3][wi] = ffma2(acc[3][wi], wb2.y, xw[kx + wi]);
                    }
                }
            }
        }

        // --- drain async stages; publish buffer ---
        if (more) cp_async_wait0();
        __syncthreads();
    }

    // --- stores: 8 co x 8 w per thread ---
    union Cv { u64 u; float2 f; };
    #pragma unroll
    for (int cp = 0; cp < 4; cp++) {
        Cv v[8];
        #pragma unroll
        for (int wi = 0; wi < 8; wi++) v[wi].u = acc[cp][wi];
        #pragma unroll
        for (int half = 0; half < 2; half++) {
            int co = co0 + 2 * cp + half;
            float* o = out + (((size_t)(b * CH + co) * HW) + y) * HW + w0;
            float4 s0, s1;
            if (half == 0) {
                s0 = make_float4(v[0].f.x, v[1].f.x, v[2].f.x, v[3].f.x);
                s1 = make_float4(v[4].f.x, v[5].f.x, v[6].f.x, v[7].f.x);
            } else {
                s0 = make_float4(v[0].f.y, v[1].f.y, v[2].f.y, v[3].f.y);
                s1 = make_float4(v[4].f.y, v[5].f.y, v[6].f.y, v[7].f.y);
            }
            *reinterpret_cast<float4*>(o)     = s0;
            *reinterpret_cast<float4*>(o + 4) = s1;
        }
    }
}

// ---------------------------------------------------------------------------
// Launch. Inputs: x, attention, weight, bias_p.
// ---------------------------------------------------------------------------
extern "C" void kernel_launch(void* const* d_in, const int* in_sizes, int n_in,
                              void* d_out, int out_size)
{
    const float* x    = (const float*)d_in[0];  // [32,64,128,128]
    const float* att  = (const float*)d_in[1];  // [32,4]
    const float* wgt  = (const float*)d_in[2];  // [4,64,64,3,3]
    const float* bias = (const float*)d_in[3];  // [4,64]
    float* out = (float*)d_out;

    const int TOT = BATCH * CH * TAPS * CH;
    mix_kernel<<<(TOT + 255) / 256, 256>>>(att, wgt, bias);

    dim3 grid(HW, BATCH);  // (y, b)
    conv_kernel<<<grid, 128>>>(x, out);
}

// round 15
// speedup vs baseline: 2.3995x; 1.0827x over previous
#include <cuda_runtime.h>
#include <cstdint>

// Problem constants
#define BATCH 32
#define CH    64
#define HW    128
#define CHW   (HW*HW)
#define NK    4
#define TAPS  9
#define CIK   (CH*TAPS)          // 576
#define CI_CHUNK 4
#define NCHUNK  (CH/CI_CHUNK)    // 16
#define WCHUNK  (CI_CHUNK*CIK)   // 2304 floats per weight chunk

// Scratch (device globals: no allocation allowed)
// g_wmix layout: [b][ci][tap][co]  (co contiguous)
__device__ float g_wmix[BATCH * CH * TAPS * CH];
__device__ float g_bmix[BATCH * CH];

// ---------------------------------------------------------------------------
// Kernel 1: mix weight bank + bias per sample
// ---------------------------------------------------------------------------
__global__ void __launch_bounds__(256) mix_kernel(
    const float* __restrict__ att,     // [B, NK]
    const float* __restrict__ weight,  // [NK, C, C, 3, 3]
    const float* __restrict__ bias)    // [NK, C]
{
    int gid = blockIdx.x * 256 + threadIdx.x;
    const int TOT = BATCH * CH * TAPS * CH;
    if (gid < TOT) {
        int b    = gid / (CH * TAPS * CH);
        int rem  = gid - b * (CH * TAPS * CH);
        int ci   = rem / (TAPS * CH);
        int rem2 = rem - ci * (TAPS * CH);
        int tap  = rem2 >> 6;
        int co   = rem2 & 63;

        float a0 = att[b * NK + 0];
        float a1 = att[b * NK + 1];
        float a2 = att[b * NK + 2];
        float a3 = att[b * NK + 3];

        int base   = ((co * CH) + ci) * TAPS + tap;
        int stride = CH * CH * TAPS;
        g_wmix[gid] = a0 * weight[base]
                    + a1 * weight[base + stride]
                    + a2 * weight[base + 2 * stride]
                    + a3 * weight[base + 3 * stride];
    }
    if (gid < BATCH * CH) {
        int b  = gid >> 6;
        int co = gid & 63;
        float s = 0.f;
        #pragma unroll
        for (int k = 0; k < NK; k++)
            s += att[b * NK + k] * bias[k * CH + co];
        g_bmix[gid] = s;
    }
}

// ---------------------------------------------------------------------------
// Kernel 2: direct 3x3 conv, FFMA2 paired over c_out, 8 c_out per thread.
// One CTA per (b, y). 128 threads: co0=(tx>>4)*8, w0=(tx&15)*8.
// Borders (cols 0/129 and y-invalid rows) are chunk-invariant zeros: both
// input buffers zeroed once, then per-chunk staging is a pure affine map
// (thread tx -> col tx of each valid row) via cp.async. Weights via cp.async.
// 4-ci chunks, double-buffered, 1 barrier/chunk (16 total).
// ---------------------------------------------------------------------------

typedef unsigned long long u64;

__device__ __forceinline__ u64 ffma2(u64 d, u64 a, u64 b) {
    asm("fma.rn.f32x2 %0, %1, %2, %0;" : "+l"(d) : "l"(a), "l"(b));
    return d;
}
__device__ __forceinline__ u64 dup2(float v) {
    u64 p;
    asm("mov.b64 %0, {%1, %1};" : "=l"(p) : "f"(v));
    return p;
}
__device__ __forceinline__ void cp_async4(unsigned saddr, const float* gaddr) {
    asm volatile("cp.async.ca.shared.global [%0], [%1], 4;"
                 :: "r"(saddr), "l"(gaddr));
}
__device__ __forceinline__ void cp_async_commit() {
    asm volatile("cp.async.commit_group;" ::: "memory");
}
__device__ __forceinline__ void cp_async_wait0() {
    asm volatile("cp.async.wait_group 0;" ::: "memory");
}

// Plain-float padded row: insert 4-float pad every 32 floats.
#define XR 148   // row stride in floats (16B multiple)
__device__ __forceinline__ int XIDX4(int c) { return c + ((c >> 5) << 2); }

__global__ void __launch_bounds__(128, 4) conv_kernel(
    const float* __restrict__ x,   // [B, C, H, W]
    float* __restrict__ out)       // [B, C, H, W]
{
    __shared__ alignas(16) float xin[2][CI_CHUNK * 3 * XR];  // 14.2 KB
    __shared__ alignas(16) float wsf[2][WCHUNK];             // 18.4 KB

    const int y  = blockIdx.x;
    const int b  = blockIdx.y;
    const int tx = threadIdx.x;

    const int co0 = (tx >> 4) << 3;  // 0..56 step 8
    const int w0  = (tx & 15) << 3;  // 0..120 step 8

    // LDS float offsets for the 3 loads of the 10-float window
    const int xo0 = XIDX4(w0);
    const int xo1 = XIDX4(w0 + 4);
    const int xo2 = XIDX4(w0 + 8);

    // Row validity (y-borders): row rr covers input row y-1+rr
    const bool vr0 = (y > 0);
    const bool vr2 = (y < HW - 1);
    const int  yo0 = (y - 1) * HW + tx;   // may be invalid; guarded
    const int  yo1 =  y      * HW + tx;
    const int  yo2 = (y + 1) * HW + tx;

    // Affine smem destination base for this thread's column (c = tx+1)
    const unsigned scol = (unsigned)(XIDX4(tx + 1) * 4);

    // Accumulators: 4 co-pairs x 8 w, init with mixed bias
    u64 acc[4][8];
    #pragma unroll
    for (int cp = 0; cp < 4; cp++) {
        u64 bp = *reinterpret_cast<const u64*>(g_bmix + b * CH + co0 + 2 * cp);
        #pragma unroll
        for (int wi = 0; wi < 8; wi++) acc[cp][wi] = bp;
    }

    const float* xbase = x + (size_t)(b * CH) * CHW;
    const float* wbase = g_wmix + (size_t)(b * CH) * TAPS * CH;
    const unsigned xin0 = (unsigned)__cvta_generic_to_shared(&xin[0][0]);
    const unsigned xin1 = (unsigned)__cvta_generic_to_shared(&xin[1][0]);
    const unsigned wsf0 = (unsigned)__cvta_generic_to_shared(&wsf[0][0]);
    const unsigned wsf1 = (unsigned)__cvta_generic_to_shared(&wsf[1][0]);

    // ---- prologue A: zero BOTH input buffers (borders + invalid rows stay 0) ----
    {
        float* base = &xin[0][0];
        const int tot = 2 * CI_CHUNK * 3 * XR;   // 3552 floats, XR*4 is 16B mult
        for (int i = tx * 4; i < tot; i += 128 * 4)
            *reinterpret_cast<float4*>(base + i) = make_float4(0.f, 0.f, 0.f, 0.f);
    }
    __syncthreads();

    // ---- prologue B: stage chunk 0 into buffer 0 ----
    {
        #pragma unroll
        for (int ci4 = 0; ci4 < CI_CHUNK; ci4++) {
            const float* xc = xbase + ci4 * CHW;
            unsigned xd = xin0 + (unsigned)(ci4 * 3 * XR * 4) + scol;
            if (vr0) cp_async4(xd,                      xc + yo0);
                     cp_async4(xd + (unsigned)(XR * 4), xc + yo1);
            if (vr2) cp_async4(xd + (unsigned)(2 * XR * 4), xc + yo2);
        }
        #pragma unroll
        for (int k = 0; k < 18; k++)
            cp_async4(wsf0 + (tx + k * 128) * 4, wbase + tx + k * 128);
        cp_async_commit();
        cp_async_wait0();
    }
    __syncthreads();

    #pragma unroll 1
    for (int chunk = 0; chunk < NCHUNK; chunk++) {
        const int p = chunk & 1;
        const bool more = (chunk + 1 < NCHUNK);

        // --- prefetch next chunk entirely via cp.async (affine map) ---
        if (more) {
            const float* xc = xbase + (chunk + 1) * CI_CHUNK * CHW;
            const unsigned xd0 = (p ? xin0 : xin1) + scol;
            #pragma unroll
            for (int ci4 = 0; ci4 < CI_CHUNK; ci4++) {
                const float* xcc = xc + ci4 * CHW;
                unsigned xd = xd0 + (unsigned)(ci4 * 3 * XR * 4);
                if (vr0) cp_async4(xd,                          xcc + yo0);
                         cp_async4(xd + (unsigned)(XR * 4),     xcc + yo1);
                if (vr2) cp_async4(xd + (unsigned)(2 * XR * 4), xcc + yo2);
            }
            const float* wc = wbase + (chunk + 1) * WCHUNK;
            const unsigned wd = p ? wsf0 : wsf1;
            #pragma unroll
            for (int k = 0; k < 18; k++)
                cp_async4(wd + (tx + k * 128) * 4, wc + tx + k * 128);
            cp_async_commit();
        }

        // --- compute 4 ci from buffer p ---
        #pragma unroll
        for (int ci4 = 0; ci4 < CI_CHUNK; ci4++) {
            const float* wr = wsf[p] + ci4 * CIK;
            const float* xb = xin[p] + ci4 * 3 * XR;
            #pragma unroll
            for (int ky = 0; ky < 3; ky++) {
                const float* xr = xb + ky * XR;
                float4 fa = *reinterpret_cast<const float4*>(xr + xo0);
                float4 fb = *reinterpret_cast<const float4*>(xr + xo1);
                float2 fc = *reinterpret_cast<const float2*>(xr + xo2);
                u64 xw[10];
                xw[0] = dup2(fa.x); xw[1] = dup2(fa.y);
                xw[2] = dup2(fa.z); xw[3] = dup2(fa.w);
                xw[4] = dup2(fb.x); xw[5] = dup2(fb.y);
                xw[6] = dup2(fb.z); xw[7] = dup2(fb.w);
                xw[8] = dup2(fc.x); xw[9] = dup2(fc.y);
                #pragma unroll
                for (int kx = 0; kx < 3; kx++) {
                    const float* wt = wr + (ky * 3 + kx) * CH + co0;
                    ulonglong2 wa  = *reinterpret_cast<const ulonglong2*>(wt);
                    ulonglong2 wb2 = *reinterpret_cast<const ulonglong2*>(wt + 4);
                    #pragma unroll
                    for (int wi = 0; wi < 8; wi++) {
                        acc[0][wi] = ffma2(acc[0][wi], wa.x,  xw[kx + wi]);
                        acc[1][wi] = ffma2(acc[1][wi], wa.y,  xw[kx + wi]);
                        acc[2][wi] = ffma2(acc[2][wi], wb2.x, xw[kx + wi]);
                        acc[3][wi] = ffma2(acc[3][wi], wb2.y, xw[kx + wi]);
                    }
                }
            }
        }

        // --- drain async stages; publish buffer ---
        if (more) cp_async_wait0();
        __syncthreads();
    }

    // --- stores: 8 co x 8 w per thread ---
    union Cv { u64 u; float2 f; };
    #pragma unroll
    for (int cp = 0; cp < 4; cp++) {
        Cv v[8];
        #pragma unroll
        for (int wi = 0; wi < 8; wi++) v[wi].u = acc[cp][wi];
        #pragma unroll
        for (int half = 0; half < 2; half++) {
            int co = co0 + 2 * cp + half;
            float* o = out + (((size_t)(b * CH + co) * HW) + y) * HW + w0;
            float4 s0, s1;
            if (half == 0) {
                s0 = make_float4(v[0].f.x, v[1].f.x, v[2].f.x, v[3].f.x);
                s1 = make_float4(v[4].f.x, v[5].f.x, v[6].f.x, v[7].f.x);
            } else {
                s0 = make_float4(v[0].f.y, v[1].f.y, v[2].f.y, v[3].f.y);
                s1 = make_float4(v[4].f.y, v[5].f.y, v[6].f.y, v[7].f.y);
            }
            *reinterpret_cast<float4*>(o)     = s0;
            *reinterpret_cast<float4*>(o + 4) = s1;
        }
    }
}

// ---------------------------------------------------------------------------
// Launch. Inputs: x, attention, weight, bias_p.
// ---------------------------------------------------------------------------
extern "C" void kernel_launch(void* const* d_in, const int* in_sizes, int n_in,
                              void* d_out, int out_size)
{
    const float* x    = (const float*)d_in[0];  // [32,64,128,128]
    const float* att  = (const float*)d_in[1];  // [32,4]
    const float* wgt  = (const float*)d_in[2];  // [4,64,64,3,3]
    const float* bias = (const float*)d_in[3];  // [4,64]
    float* out = (float*)d_out;

    const int TOT = BATCH * CH * TAPS * CH;
    mix_kernel<<<(TOT + 255) / 256, 256>>>(att, wgt, bias);

    dim3 grid(HW, BATCH);  // (y, b)
    conv_kernel<<<grid, 128>>>(x, out);
}